// round 9
// baseline (speedup 1.0000x reference)
#include <cuda_runtime.h>
#include <math.h>
#include <cstdint>

#define EPSF 1e-5f

// Problem constants
#define BATCH 32
#define CIN   512
#define COUT  512
#define HW    3136   // 56*56
#define KNUM  4
#define ADIM  32

#define NMT  (COUT / 16)   // 32 m-tiles
#define NKT8 (CIN / 8)     // 64 k8-tiles
#define NTP  (HW / 16)     // 196 n-tile-pairs

// GEMM tiling
#define BM 128
#define BN 128
#define BKK 32
#define NIT (CIN / BKK)          // 16 mainloop iterations
#define STAGES 3
#define A_STAGE_FLOATS (8 * 4 * 32 * 4)    // 4096
#define B_STAGE_FLOATS (4 * 8 * 32 * 4)    // 4096
#define STAGE_FLOATS (A_STAGE_FLOATS + B_STAGE_FLOATS)
#define GEMM_SMEM_BYTES (STAGES * STAGE_FLOATS * 4)   // 98304 B

// ---------------- device scratch ----------------
__device__ float g_pooled[BATCH * CIN];
__device__ float g_ch[BATCH * CIN];
__device__ float g_rowscale[BATCH * COUT];
__device__ float g_kn[BATCH * KNUM];
__device__ float g_bias[COUT];
__device__ float g_weff[BATCH * NMT * NKT8 * 32 * 4];
__device__ float g_xpack[(size_t)BATCH * NKT8 * NTP * 32 * 4];

// ================= helpers =================
__device__ __forceinline__ float cvt_tf32(float v) {
    uint32_t u;
    asm("cvt.rna.tf32.f32 %0, %1;" : "=r"(u) : "f"(v));
    return __uint_as_float(u);
}

__device__ __forceinline__ void cp16(float* smem_dst, const float* gsrc, bool pred) {
    uint32_t s;
    asm("{ .reg .u64 t; cvta.to.shared.u64 t, %1; cvt.u32.u64 %0, t; }"
        : "=r"(s) : "l"(smem_dst));
    int sz = pred ? 16 : 0;
    asm volatile("cp.async.cg.shared.global [%0], [%1], 16, %2;"
                 :: "r"(s), "l"(gsrc), "r"(sz) : "memory");
}
#define CP_COMMIT() asm volatile("cp.async.commit_group;" ::: "memory")
#define CP_WAIT(n)  asm volatile("cp.async.wait_group %0;" :: "n"(n) : "memory")

__device__ __forceinline__ void mma16n8k8(float (&d)[4], const uint32_t a0, const uint32_t a1,
                                          const uint32_t a2, const uint32_t a3,
                                          const uint32_t b0, const uint32_t b1) {
    asm volatile(
        "mma.sync.aligned.m16n8k8.row.col.f32.tf32.tf32.f32 "
        "{%0,%1,%2,%3}, {%4,%5,%6,%7}, {%8,%9}, {%0,%1,%2,%3};"
        : "+f"(d[0]), "+f"(d[1]), "+f"(d[2]), "+f"(d[3])
        : "r"(a0), "r"(a1), "r"(a2), "r"(a3), "r"(b0), "r"(b1));
}

__device__ __forceinline__ float warp_sum(float v) {
    #pragma unroll
    for (int off = 16; off > 0; off >>= 1)
        v += __shfl_xor_sync(0xffffffffu, v, off);
    return v;
}

// ---------------- Kernel P: global average pool (main stream) --------------
__global__ void pool_kernel(const float* __restrict__ x) {
    int row = blockIdx.x * 8 + (threadIdx.x >> 5);
    int lane = threadIdx.x & 31;
    if (row >= BATCH * CIN) return;
    const float4* p = reinterpret_cast<const float4*>(x + (size_t)row * HW);
    float s = 0.f;
    for (int i = lane; i < HW / 4; i += 32) {
        float4 v = p[i];
        s += v.x + v.y + v.z + v.w;
    }
    s = warp_sum(s);
    if (lane == 0) g_pooled[row] = s * (1.0f / HW);
}

// ---------------- Kernel A: prepack x -> tf32 B-fragments (side stream) ----
#define CHUNK 1024
__global__ __launch_bounds__(256)
void prepack_kernel(const float* __restrict__ x) {
    __shared__ float sx[8][CHUNK + 8];

    const int bx  = blockIdx.x;
    const int b   = bx >> 6;
    const int kt8 = bx & 63;
    const int tid = threadIdx.x;
    const int lane = tid & 31;
    const int w    = tid >> 5;

    const float* Xr = x + ((size_t)b * CIN + kt8 * 8) * HW;
    float4* Op = reinterpret_cast<float4*>(g_xpack) +
                 ((size_t)(b * NKT8 + kt8) * NTP) * 32;

    const int tg  = lane & 3;
    const int gid = lane >> 2;

    for (int n0 = 0; n0 < HW; n0 += CHUNK) {
        // warp w loads row w: 8 float4 per lane, fully coalesced
        #pragma unroll
        for (int i = 0; i < 8; i++) {
            const int col = lane * 4 + i * 128;
            float4 v = make_float4(0.f, 0.f, 0.f, 0.f);
            if (n0 + col < HW)
                v = *reinterpret_cast<const float4*>(&Xr[(size_t)w * HW + n0 + col]);
            *reinterpret_cast<float4*>(&sx[w][col]) = v;
        }
        __syncthreads();

        const int ntps = min(CHUNK, HW - n0) >> 4;   // 64 or 4
        #pragma unroll
        for (int r = 0; r < 8; r++) {
            const int f = tid + 256 * r;
            const int ntpl = f >> 5;
            if (ntpl < ntps) {
                const int col0 = ntpl * 16 + gid;
                const int col1 = col0 + 8;
                float4 o;
                o.x = cvt_tf32(sx[tg][col0]);
                o.y = cvt_tf32(sx[tg + 4][col0]);
                o.z = cvt_tf32(sx[tg][col1]);
                o.w = cvt_tf32(sx[tg + 4][col1]);
                Op[(size_t)((n0 >> 4) + ntpl) * 32 + lane] = o;
            }
        }
        __syncthreads();
    }
}

// ---------------- Kernel B: attention heads ----------
__global__ __launch_bounds__(256)
void attn_kernel(const float* __restrict__ fc_w,
                 const float* __restrict__ abn_g, const float* __restrict__ abn_b,
                 const float* __restrict__ abn_m, const float* __restrict__ abn_v,
                 const float* __restrict__ ch_w, const float* __restrict__ ch_b,
                 const float* __restrict__ fl_w, const float* __restrict__ fl_b,
                 const float* __restrict__ kn_w, const float* __restrict__ kn_b,
                 const float* __restrict__ bn_g, const float* __restrict__ bn_b,
                 const float* __restrict__ bn_m, const float* __restrict__ bn_v) {
    __shared__ float sp[CIN];
    __shared__ float sh[ADIM];
    __shared__ float slog[KNUM];

    const int b = blockIdx.x;
    const int tid = threadIdx.x;
    const int wid = tid >> 5;
    const int lane = tid & 31;

    #pragma unroll
    for (int i = 0; i < CIN / 256; i++)
        sp[tid + 256 * i] = g_pooled[b * CIN + tid + 256 * i];
    __syncthreads();

    #pragma unroll
    for (int i = 0; i < 4; i++) {
        const int a = wid + 8 * i;
        const float* fr = &fc_w[a * CIN];
        float s = 0.f;
        #pragma unroll
        for (int c = 0; c < CIN / 32; c++)
            s += sp[lane + 32 * c] * fr[lane + 32 * c];
        s = warp_sum(s);
        if (lane == 0) {
            float inv_a = abn_g[a] * rsqrtf(abn_v[a] + EPSF);
            s = (s - abn_m[a]) * inv_a + abn_b[a];
            sh[a] = fmaxf(s, 0.f);
        }
    }
    __syncthreads();

    const float hv = sh[lane];

    for (int i = 0; i < 64; i++) {
        const int c = wid * 64 + i;
        float s = warp_sum(hv * ch_w[c * ADIM + lane]);
        if (lane == 0)
            g_ch[b * CIN + c] = 1.0f / (1.0f + __expf(-(s + ch_b[c])));
    }
    for (int i = 0; i < 64; i++) {
        const int o = wid * 64 + i;
        float s = warp_sum(hv * fl_w[o * ADIM + lane]);
        if (lane == 0) {
            float fl = 1.0f / (1.0f + __expf(-(s + fl_b[o])));
            g_rowscale[b * COUT + o] = fl * bn_g[o] * rsqrtf(bn_v[o] + EPSF);
        }
    }
    if (wid == 0) {
        #pragma unroll
        for (int kk = 0; kk < KNUM; kk++) {
            float s = warp_sum(hv * kn_w[kk * ADIM + lane]);
            if (lane == 0) slog[kk] = s + kn_b[kk];
        }
        __syncwarp();
        if (lane == 0) {
            float m = fmaxf(fmaxf(slog[0], slog[1]), fmaxf(slog[2], slog[3]));
            float e0 = __expf(slog[0] - m), e1 = __expf(slog[1] - m);
            float e2 = __expf(slog[2] - m), e3 = __expf(slog[3] - m);
            float d = 1.0f / (e0 + e1 + e2 + e3);
            g_kn[b * KNUM + 0] = e0 * d;
            g_kn[b * KNUM + 1] = e1 * d;
            g_kn[b * KNUM + 2] = e2 * d;
            g_kn[b * KNUM + 3] = e3 * d;
        }
    }
    if (b == 0) {
        #pragma unroll
        for (int i = 0; i < COUT / 256; i++) {
            int o = tid + 256 * i;
            float inv = bn_g[o] * rsqrtf(bn_v[o] + EPSF);
            g_bias[o] = bn_b[o] - bn_m[o] * inv;
        }
    }
}

// ---------------- Kernel C: effective weight, batch-looped ----------------
__global__ __launch_bounds__(256)
void weff_kernel(const float* __restrict__ weight) {
    const int idx = blockIdx.x * 256 + threadIdx.x;   // (mt, kt8, lane)
    const int lane = idx & 31;
    const int kt8 = (idx >> 5) & (NKT8 - 1);
    const int mt  = idx >> 11;

    const int gid = lane >> 2;
    const int tg  = lane & 3;
    const int o  = mt * 16 + gid;
    const int k  = kt8 * 8 + tg;

    float w[4][4];
    #pragma unroll
    for (int j = 0; j < KNUM; j++) {
        const float* wj = weight + ((size_t)j * COUT) * CIN;
        w[j][0] = wj[(size_t)o * CIN + k];
        w[j][1] = wj[(size_t)(o + 8) * CIN + k];
        w[j][2] = wj[(size_t)o * CIN + k + 4];
        w[j][3] = wj[(size_t)(o + 8) * CIN + k + 4];
    }

    float4* out = reinterpret_cast<float4*>(g_weff);
    #pragma unroll 4
    for (int b = 0; b < BATCH; b++) {
        const float kn0 = g_kn[b * KNUM + 0], kn1 = g_kn[b * KNUM + 1];
        const float kn2 = g_kn[b * KNUM + 2], kn3 = g_kn[b * KNUM + 3];
        const float rs0 = g_rowscale[b * COUT + o];
        const float rs1 = g_rowscale[b * COUT + o + 8];
        const float ch0 = g_ch[b * CIN + k];
        const float ch1 = g_ch[b * CIN + k + 4];

        float4 v;
        v.x = cvt_tf32(rs0 * ch0 * (kn0 * w[0][0] + kn1 * w[1][0] + kn2 * w[2][0] + kn3 * w[3][0]));
        v.y = cvt_tf32(rs1 * ch0 * (kn0 * w[0][1] + kn1 * w[1][1] + kn2 * w[2][1] + kn3 * w[3][1]));
        v.z = cvt_tf32(rs0 * ch1 * (kn0 * w[0][2] + kn1 * w[1][2] + kn2 * w[2][2] + kn3 * w[3][2]));
        v.w = cvt_tf32(rs1 * ch1 * (kn0 * w[0][3] + kn1 * w[1][3] + kn2 * w[2][3] + kn3 * w[3][3]));
        out[((size_t)(b * NMT + mt) * NKT8 + kt8) * 32 + lane] = v;
    }
}

// ---------------- Kernel D: mma.sync tf32 GEMM, both operands frag-packed ----
__global__ __launch_bounds__(256, 2)
void gemm_mma_kernel(float* __restrict__ y) {
    extern __shared__ float smem[];

    const int tid  = threadIdx.x;
    const int lane = tid & 31;
    const int wid  = tid >> 5;
    const int wm   = wid >> 2;
    const int wn   = wid & 3;
    const int gid  = lane >> 2;
    const int tg   = lane & 3;

    const int mt0 = blockIdx.x * (BM / 16);
    const int o0  = blockIdx.x * BM;
    const int hw0 = blockIdx.y * BN;
    const int ntp0 = blockIdx.y * (BN / 16);
    const int b   = blockIdx.z;

    const float4* Wg4 = reinterpret_cast<const float4*>(g_weff);
    size_t a_g[4];
    #pragma unroll
    for (int r = 0; r < 4; r++) {
        const int f = tid + 256 * r;
        const int mt = f >> 7, kt8l = (f >> 5) & 3, ln = f & 31;
        a_g[r] = ((size_t)(b * NMT + mt0 + mt) * NKT8 + kt8l) * 32 + ln;
    }
    const float4* Xp4 = reinterpret_cast<const float4*>(g_xpack);
    size_t b_g[4];
    bool b_pred[4];
    #pragma unroll
    for (int r = 0; r < 4; r++) {
        const int f = tid + 256 * r;
        const int kt8l = f >> 8, ntp = (f >> 5) & 7, ln = f & 31;
        b_g[r] = ((size_t)(b * NKT8 + kt8l) * NTP + ntp0 + ntp) * 32 + ln;
        b_pred[r] = (ntp0 + ntp) < NTP;
    }

    float acc[4][4][4];
    #pragma unroll
    for (int mi = 0; mi < 4; mi++)
        #pragma unroll
        for (int ni = 0; ni < 4; ni++)
            #pragma unroll
            for (int r = 0; r < 4; r++) acc[mi][ni][r] = 0.f;

    #pragma unroll
    for (int s = 0; s < STAGES - 1; s++) {
        float* As = smem + s * STAGE_FLOATS;
        float* Bs = As + A_STAGE_FLOATS;
        #pragma unroll
        for (int r = 0; r < 4; r++) {
            const int f = tid + 256 * r;
            cp16(&As[f * 4], (const float*)(Wg4 + a_g[r] + (size_t)s * 128), true);
            cp16(&Bs[f * 4], (const float*)(Xp4 + b_g[r] + (size_t)s * 4 * NTP * 32), b_pred[r]);
        }
        CP_COMMIT();
    }

    int cur = 0;
    for (int kc = 0; kc < NIT; kc++) {
        if (kc + 2 < NIT) { CP_WAIT(1); } else { CP_WAIT(0); }
        __syncthreads();

        if (kc + 2 < NIT) {
            int s = cur + 2; if (s >= STAGES) s -= STAGES;
            float* As = smem + s * STAGE_FLOATS;
            float* Bs = As + A_STAGE_FLOATS;
            #pragma unroll
            for (int r = 0; r < 4; r++) {
                const int f = tid + 256 * r;
                cp16(&As[f * 4], (const float*)(Wg4 + a_g[r] + (size_t)(kc + 2) * 128), true);
                cp16(&Bs[f * 4], (const float*)(Xp4 + b_g[r] + (size_t)(kc + 2) * 4 * NTP * 32), b_pred[r]);
            }
            CP_COMMIT();
        }

        const float* As = smem + cur * STAGE_FLOATS;
        const float4* Af = reinterpret_cast<const float4*>(As);
        const float4* Bf4 = reinterpret_cast<const float4*>(As + A_STAGE_FLOATS);

        #pragma unroll
        for (int kt = 0; kt < 4; kt++) {
            float4 af[4];
            #pragma unroll
            for (int mi = 0; mi < 4; mi++)
                af[mi] = Af[((wm * 4 + mi) * 4 + kt) * 32 + lane];
            float4 bp[2];
            #pragma unroll
            for (int p = 0; p < 2; p++)
                bp[p] = Bf4[((kt * 8) + wn * 2 + p) * 32 + lane];
            uint32_t bfr[4][2];
            bfr[0][0] = __float_as_uint(bp[0].x); bfr[0][1] = __float_as_uint(bp[0].y);
            bfr[1][0] = __float_as_uint(bp[0].z); bfr[1][1] = __float_as_uint(bp[0].w);
            bfr[2][0] = __float_as_uint(bp[1].x); bfr[2][1] = __float_as_uint(bp[1].y);
            bfr[3][0] = __float_as_uint(bp[1].z); bfr[3][1] = __float_as_uint(bp[1].w);
            #pragma unroll
            for (int mi = 0; mi < 4; mi++) {
                const uint32_t a0 = __float_as_uint(af[mi].x);
                const uint32_t a1 = __float_as_uint(af[mi].y);
                const uint32_t a2 = __float_as_uint(af[mi].z);
                const uint32_t a3 = __float_as_uint(af[mi].w);
                #pragma unroll
                for (int ni = 0; ni < 4; ni++)
                    mma16n8k8(acc[mi][ni], a0, a1, a2, a3, bfr[ni][0], bfr[ni][1]);
            }
        }
        cur++; if (cur == STAGES) cur = 0;
    }

    #pragma unroll
    for (int mi = 0; mi < 4; mi++) {
        const int row = o0 + wm * 64 + mi * 16 + gid;
        const float bias0 = g_bias[row];
        const float bias1 = g_bias[row + 8];
        float* y0 = y + ((size_t)b * COUT + row) * HW;
        #pragma unroll
        for (int ni = 0; ni < 4; ni++) {
            const int col = hw0 + (wn * 4 + ni) * 8 + tg * 2;
            if (col < HW) {
                float2 v0 = make_float2(acc[mi][ni][0] + bias0, acc[mi][ni][1] + bias0);
                float2 v1 = make_float2(acc[mi][ni][2] + bias1, acc[mi][ni][3] + bias1);
                *reinterpret_cast<float2*>(y0 + col) = v0;
                *reinterpret_cast<float2*>(y0 + (size_t)8 * HW + col) = v1;
            }
        }
    }
}

// ---------------- launch (fork-join graph) ----------------
extern "C" void kernel_launch(void* const* d_in, const int* in_sizes, int n_in,
                              void* d_out, int out_size) {
    const float* x    = (const float*)d_in[0];
    const float* fc_w = (const float*)d_in[1];
    const float* abn_g = (const float*)d_in[2];
    const float* abn_b = (const float*)d_in[3];
    const float* abn_m = (const float*)d_in[4];
    const float* abn_v = (const float*)d_in[5];
    const float* ch_w = (const float*)d_in[6];
    const float* ch_b = (const float*)d_in[7];
    const float* fl_w = (const float*)d_in[8];
    const float* fl_b = (const float*)d_in[9];
    const float* kn_w = (const float*)d_in[10];
    const float* kn_b = (const float*)d_in[11];
    const float* weight = (const float*)d_in[12];
    const float* bn_g = (const float*)d_in[13];
    const float* bn_b = (const float*)d_in[14];
    const float* bn_m = (const float*)d_in[15];
    const float* bn_v = (const float*)d_in[16];
    float* y = (float*)d_out;

    static cudaStream_t s_side = nullptr;
    static cudaEvent_t s_fork = nullptr, s_join = nullptr;
    if (s_side == nullptr) {
        cudaStreamCreateWithFlags(&s_side, cudaStreamNonBlocking);
        cudaEventCreateWithFlags(&s_fork, cudaEventDisableTiming);
        cudaEventCreateWithFlags(&s_join, cudaEventDisableTiming);
        cudaFuncSetAttribute(gemm_mma_kernel,
                             cudaFuncAttributeMaxDynamicSharedMemorySize, GEMM_SMEM_BYTES);
    }

    // fork: side stream does prepack(x) in parallel with pool->attn->weff
    cudaEventRecord(s_fork, 0);
    cudaStreamWaitEvent(s_side, s_fork, 0);

    prepack_kernel<<<BATCH * NKT8, 256, 0, s_side>>>(x);

    pool_kernel<<<BATCH * CIN / 8, 256>>>(x);
    attn_kernel<<<BATCH, 256>>>(fc_w, abn_g, abn_b, abn_m, abn_v,
                                ch_w, ch_b, fl_w, fl_b, kn_w, kn_b,
                                bn_g, bn_b, bn_m, bn_v);
    weff_kernel<<<NMT * NKT8 * 32 / 256, 256>>>(weight);

    // join
    cudaEventRecord(s_join, s_side);
    cudaStreamWaitEvent(0, s_join, 0);

    dim3 grid(COUT / BM, (HW + BN - 1) / BN, BATCH);  // (4, 25, 32)
    gemm_mma_kernel<<<grid, 256, GEMM_SMEM_BYTES>>>(y);
}

// round 10
// speedup vs baseline: 1.1044x; 1.1044x over previous
#include <cuda_runtime.h>
#include <math.h>
#include <cstdint>

#define EPSF 1e-5f

// Problem constants
#define BATCH 32
#define CIN   512
#define COUT  512
#define HW    3136   // 56*56
#define KNUM  4
#define ADIM  32

#define NMT  (COUT / 16)   // 32 m-tiles
#define NKT8 (CIN / 8)     // 64 k8-tiles
#define NTP  (HW / 16)     // 196 n-tile-pairs

// GEMM tiling
#define BM 128
#define BN 128
#define BKK 32
#define NIT (CIN / BKK)          // 16 mainloop iterations
#define STAGES 3
#define A_STAGE_FLOATS (8 * 4 * 32 * 4)    // 4096
#define B_STAGE_FLOATS (4 * 8 * 32 * 4)    // 4096
#define STAGE_FLOATS (A_STAGE_FLOATS + B_STAGE_FLOATS)
#define GEMM_SMEM_BYTES (STAGES * STAGE_FLOATS * 4)   // 98304 B

// ---------------- device scratch ----------------
__device__ float g_pooled[BATCH * CIN];
__device__ float g_ch[BATCH * CIN];
__device__ float g_rowscale[BATCH * COUT];
__device__ float g_kn[BATCH * KNUM];
__device__ float g_bias[COUT];
__device__ float g_weff[BATCH * NMT * NKT8 * 32 * 4];
__device__ float g_xpack[(size_t)BATCH * NKT8 * NTP * 32 * 4];

// ================= helpers =================
__device__ __forceinline__ float cvt_tf32(float v) {
    uint32_t u;
    asm("cvt.rna.tf32.f32 %0, %1;" : "=r"(u) : "f"(v));
    return __uint_as_float(u);
}

__device__ __forceinline__ void cp16(float* smem_dst, const float* gsrc, bool pred) {
    uint32_t s;
    asm("{ .reg .u64 t; cvta.to.shared.u64 t, %1; cvt.u32.u64 %0, t; }"
        : "=r"(s) : "l"(smem_dst));
    int sz = pred ? 16 : 0;
    asm volatile("cp.async.cg.shared.global [%0], [%1], 16, %2;"
                 :: "r"(s), "l"(gsrc), "r"(sz) : "memory");
}
#define CP_COMMIT() asm volatile("cp.async.commit_group;" ::: "memory")
#define CP_WAIT(n)  asm volatile("cp.async.wait_group %0;" :: "n"(n) : "memory")

__device__ __forceinline__ void mma16n8k8(float (&d)[4], const uint32_t a0, const uint32_t a1,
                                          const uint32_t a2, const uint32_t a3,
                                          const uint32_t b0, const uint32_t b1) {
    asm volatile(
        "mma.sync.aligned.m16n8k8.row.col.f32.tf32.tf32.f32 "
        "{%0,%1,%2,%3}, {%4,%5,%6,%7}, {%8,%9}, {%0,%1,%2,%3};"
        : "+f"(d[0]), "+f"(d[1]), "+f"(d[2]), "+f"(d[3])
        : "r"(a0), "r"(a1), "r"(a2), "r"(a3), "r"(b0), "r"(b1));
}

__device__ __forceinline__ float warp_sum(float v) {
    #pragma unroll
    for (int off = 16; off > 0; off >>= 1)
        v += __shfl_xor_sync(0xffffffffu, v, off);
    return v;
}

// ---------------- Kernel A: prepack x -> tf32 B-fragments (paired) + pool ----
#define CHUNK 512
__global__ __launch_bounds__(256)
void prepack_kernel(const float* __restrict__ x) {
    __shared__ float sx[8][520];
    __shared__ float sred[8][4];

    const int bx  = blockIdx.x;
    const int b   = bx >> 6;
    const int kt8 = bx & 63;
    const int tid = threadIdx.x;
    const int lane = tid & 31;
    const int w    = tid >> 5;

    const float* Xr = x + ((size_t)b * CIN + kt8 * 8) * HW;
    float4* Op = reinterpret_cast<float4*>(g_xpack) +
                 ((size_t)(b * NKT8 + kt8) * NTP) * 32;

    const int l_row  = tid >> 7;            // 0..1
    const int l_col4 = (tid & 127) * 4;
    float psum[4] = {0.f, 0.f, 0.f, 0.f};

    const int tg  = lane & 3;
    const int gid = lane >> 2;

    for (int n0 = 0; n0 < HW; n0 += CHUNK) {
        #pragma unroll
        for (int r = 0; r < 4; r++) {
            const int row = 2 * r + l_row;
            float4 v = make_float4(0.f, 0.f, 0.f, 0.f);
            if (n0 + l_col4 < HW)
                v = *reinterpret_cast<const float4*>(&Xr[(size_t)row * HW + n0 + l_col4]);
            psum[r] += v.x + v.y + v.z + v.w;
            *reinterpret_cast<float4*>(&sx[row][l_col4]) = v;
        }
        __syncthreads();

        const int ntps = min(CHUNK, HW - n0) >> 4;   // 32 or 4
        #pragma unroll
        for (int r = 0; r < 4; r++) {
            const int f = tid + 256 * r;
            const int ntpl = f >> 5;
            if (ntpl < ntps) {
                const int col0 = ntpl * 16 + gid;
                const int col1 = col0 + 8;
                float4 o;
                o.x = cvt_tf32(sx[tg][col0]);
                o.y = cvt_tf32(sx[tg + 4][col0]);
                o.z = cvt_tf32(sx[tg][col1]);
                o.w = cvt_tf32(sx[tg + 4][col1]);
                Op[(size_t)((n0 >> 4) + ntpl) * 32 + lane] = o;
            }
        }
        __syncthreads();
    }

    #pragma unroll
    for (int r = 0; r < 4; r++) {
        float s = warp_sum(psum[r]);
        if (lane == 0) sred[2 * r + (w >> 2)][w & 3] = s;
    }
    __syncthreads();
    if (tid < 8) {
        float s = sred[tid][0] + sred[tid][1] + sred[tid][2] + sred[tid][3];
        g_pooled[b * CIN + kt8 * 8 + tid] = s * (1.0f / HW);
    }
}

// ---------------- Kernel B: attention heads ----------
__global__ __launch_bounds__(256)
void attn_kernel(const float* __restrict__ fc_w,
                 const float* __restrict__ abn_g, const float* __restrict__ abn_b,
                 const float* __restrict__ abn_m, const float* __restrict__ abn_v,
                 const float* __restrict__ ch_w, const float* __restrict__ ch_b,
                 const float* __restrict__ fl_w, const float* __restrict__ fl_b,
                 const float* __restrict__ kn_w, const float* __restrict__ kn_b,
                 const float* __restrict__ bn_g, const float* __restrict__ bn_b,
                 const float* __restrict__ bn_m, const float* __restrict__ bn_v) {
    __shared__ float sp[CIN];
    __shared__ float sh[ADIM];
    __shared__ float slog[KNUM];

    const int b = blockIdx.x;
    const int tid = threadIdx.x;
    const int wid = tid >> 5;
    const int lane = tid & 31;

    #pragma unroll
    for (int i = 0; i < CIN / 256; i++)
        sp[tid + 256 * i] = g_pooled[b * CIN + tid + 256 * i];
    __syncthreads();

    #pragma unroll
    for (int i = 0; i < 4; i++) {
        const int a = wid + 8 * i;
        const float* fr = &fc_w[a * CIN];
        float s = 0.f;
        #pragma unroll
        for (int c = 0; c < CIN / 32; c++)
            s += sp[lane + 32 * c] * fr[lane + 32 * c];
        s = warp_sum(s);
        if (lane == 0) {
            float inv_a = abn_g[a] * rsqrtf(abn_v[a] + EPSF);
            s = (s - abn_m[a]) * inv_a + abn_b[a];
            sh[a] = fmaxf(s, 0.f);
        }
    }
    __syncthreads();

    const float hv = sh[lane];

    for (int i = 0; i < 64; i++) {
        const int c = wid * 64 + i;
        float s = warp_sum(hv * ch_w[c * ADIM + lane]);
        if (lane == 0)
            g_ch[b * CIN + c] = 1.0f / (1.0f + __expf(-(s + ch_b[c])));
    }
    for (int i = 0; i < 64; i++) {
        const int o = wid * 64 + i;
        float s = warp_sum(hv * fl_w[o * ADIM + lane]);
        if (lane == 0) {
            float fl = 1.0f / (1.0f + __expf(-(s + fl_b[o])));
            g_rowscale[b * COUT + o] = fl * bn_g[o] * rsqrtf(bn_v[o] + EPSF);
        }
    }
    if (wid == 0) {
        #pragma unroll
        for (int kk = 0; kk < KNUM; kk++) {
            float s = warp_sum(hv * kn_w[kk * ADIM + lane]);
            if (lane == 0) slog[kk] = s + kn_b[kk];
        }
        __syncwarp();
        if (lane == 0) {
            float m = fmaxf(fmaxf(slog[0], slog[1]), fmaxf(slog[2], slog[3]));
            float e0 = __expf(slog[0] - m), e1 = __expf(slog[1] - m);
            float e2 = __expf(slog[2] - m), e3 = __expf(slog[3] - m);
            float d = 1.0f / (e0 + e1 + e2 + e3);
            g_kn[b * KNUM + 0] = e0 * d;
            g_kn[b * KNUM + 1] = e1 * d;
            g_kn[b * KNUM + 2] = e2 * d;
            g_kn[b * KNUM + 3] = e3 * d;
        }
    }
    if (b == 0) {
        #pragma unroll
        for (int i = 0; i < COUT / 256; i++) {
            int o = tid + 256 * i;
            float inv = bn_g[o] * rsqrtf(bn_v[o] + EPSF);
            g_bias[o] = bn_b[o] - bn_m[o] * inv;
        }
    }
}

// ---------------- Kernel C: effective weight, 4-way batch-split ----------------
// gidx = (bq, mt, kt8, lane); each thread covers 8 batches bq*8..bq*8+7
__global__ __launch_bounds__(256)
void weff_kernel(const float* __restrict__ weight) {
    const int gidx = blockIdx.x * 256 + threadIdx.x;
    const int lane = gidx & 31;
    const int kt8 = (gidx >> 5) & (NKT8 - 1);
    const int mt  = (gidx >> 11) & (NMT - 1);
    const int bq  = gidx >> 16;            // 0..3

    const int gid = lane >> 2;
    const int tg  = lane & 3;
    const int o  = mt * 16 + gid;
    const int k  = kt8 * 8 + tg;

    float w[4][4];
    #pragma unroll
    for (int j = 0; j < KNUM; j++) {
        const float* wj = weight + ((size_t)j * COUT) * CIN;
        w[j][0] = wj[(size_t)o * CIN + k];
        w[j][1] = wj[(size_t)(o + 8) * CIN + k];
        w[j][2] = wj[(size_t)o * CIN + k + 4];
        w[j][3] = wj[(size_t)(o + 8) * CIN + k + 4];
    }

    float4* out = reinterpret_cast<float4*>(g_weff);
    const int b0 = bq * 8;
    #pragma unroll
    for (int bb = 0; bb < 8; bb++) {
        const int b = b0 + bb;
        const float kn0 = g_kn[b * KNUM + 0], kn1 = g_kn[b * KNUM + 1];
        const float kn2 = g_kn[b * KNUM + 2], kn3 = g_kn[b * KNUM + 3];
        const float rs0 = g_rowscale[b * COUT + o];
        const float rs1 = g_rowscale[b * COUT + o + 8];
        const float ch0 = g_ch[b * CIN + k];
        const float ch1 = g_ch[b * CIN + k + 4];

        float4 v;
        v.x = cvt_tf32(rs0 * ch0 * (kn0 * w[0][0] + kn1 * w[1][0] + kn2 * w[2][0] + kn3 * w[3][0]));
        v.y = cvt_tf32(rs1 * ch0 * (kn0 * w[0][1] + kn1 * w[1][1] + kn2 * w[2][1] + kn3 * w[3][1]));
        v.z = cvt_tf32(rs0 * ch1 * (kn0 * w[0][2] + kn1 * w[1][2] + kn2 * w[2][2] + kn3 * w[3][2]));
        v.w = cvt_tf32(rs1 * ch1 * (kn0 * w[0][3] + kn1 * w[1][3] + kn2 * w[2][3] + kn3 * w[3][3]));
        out[((size_t)(b * NMT + mt) * NKT8 + kt8) * 32 + lane] = v;
    }
}

// ---------------- Kernel D: mma.sync tf32 GEMM, both operands frag-packed ----
__global__ __launch_bounds__(256, 2)
void gemm_mma_kernel(float* __restrict__ y) {
    extern __shared__ float smem[];

    const int tid  = threadIdx.x;
    const int lane = tid & 31;
    const int wid  = tid >> 5;
    const int wm   = wid >> 2;
    const int wn   = wid & 3;
    const int gid  = lane >> 2;
    const int tg   = lane & 3;

    const int mt0 = blockIdx.x * (BM / 16);
    const int o0  = blockIdx.x * BM;
    const int hw0 = blockIdx.y * BN;
    const int ntp0 = blockIdx.y * (BN / 16);
    const int b   = blockIdx.z;

    const float4* Wg4 = reinterpret_cast<const float4*>(g_weff);
    size_t a_g[4];
    #pragma unroll
    for (int r = 0; r < 4; r++) {
        const int f = tid + 256 * r;
        const int mt = f >> 7, kt8l = (f >> 5) & 3, ln = f & 31;
        a_g[r] = ((size_t)(b * NMT + mt0 + mt) * NKT8 + kt8l) * 32 + ln;
    }
    const float4* Xp4 = reinterpret_cast<const float4*>(g_xpack);
    size_t b_g[4];
    bool b_pred[4];
    #pragma unroll
    for (int r = 0; r < 4; r++) {
        const int f = tid + 256 * r;
        const int kt8l = f >> 8, ntp = (f >> 5) & 7, ln = f & 31;
        b_g[r] = ((size_t)(b * NKT8 + kt8l) * NTP + ntp0 + ntp) * 32 + ln;
        b_pred[r] = (ntp0 + ntp) < NTP;
    }

    float acc[4][4][4];
    #pragma unroll
    for (int mi = 0; mi < 4; mi++)
        #pragma unroll
        for (int ni = 0; ni < 4; ni++)
            #pragma unroll
            for (int r = 0; r < 4; r++) acc[mi][ni][r] = 0.f;

    #pragma unroll
    for (int s = 0; s < STAGES - 1; s++) {
        float* As = smem + s * STAGE_FLOATS;
        float* Bs = As + A_STAGE_FLOATS;
        #pragma unroll
        for (int r = 0; r < 4; r++) {
            const int f = tid + 256 * r;
            cp16(&As[f * 4], (const float*)(Wg4 + a_g[r] + (size_t)s * 128), true);
            cp16(&Bs[f * 4], (const float*)(Xp4 + b_g[r] + (size_t)s * 4 * NTP * 32), b_pred[r]);
        }
        CP_COMMIT();
    }

    int cur = 0;
    for (int kc = 0; kc < NIT; kc++) {
        if (kc + 2 < NIT) { CP_WAIT(1); } else { CP_WAIT(0); }
        __syncthreads();

        if (kc + 2 < NIT) {
            int s = cur + 2; if (s >= STAGES) s -= STAGES;
            float* As = smem + s * STAGE_FLOATS;
            float* Bs = As + A_STAGE_FLOATS;
            #pragma unroll
            for (int r = 0; r < 4; r++) {
                const int f = tid + 256 * r;
                cp16(&As[f * 4], (const float*)(Wg4 + a_g[r] + (size_t)(kc + 2) * 128), true);
                cp16(&Bs[f * 4], (const float*)(Xp4 + b_g[r] + (size_t)(kc + 2) * 4 * NTP * 32), b_pred[r]);
            }
            CP_COMMIT();
        }

        const float* As = smem + cur * STAGE_FLOATS;
        const float4* Af = reinterpret_cast<const float4*>(As);
        const float4* Bf4 = reinterpret_cast<const float4*>(As + A_STAGE_FLOATS);

        #pragma unroll
        for (int kt = 0; kt < 4; kt++) {
            float4 af[4];
            #pragma unroll
            for (int mi = 0; mi < 4; mi++)
                af[mi] = Af[((wm * 4 + mi) * 4 + kt) * 32 + lane];
            float4 bp[2];
            #pragma unroll
            for (int p = 0; p < 2; p++)
                bp[p] = Bf4[((kt * 8) + wn * 2 + p) * 32 + lane];
            uint32_t bfr[4][2];
            bfr[0][0] = __float_as_uint(bp[0].x); bfr[0][1] = __float_as_uint(bp[0].y);
            bfr[1][0] = __float_as_uint(bp[0].z); bfr[1][1] = __float_as_uint(bp[0].w);
            bfr[2][0] = __float_as_uint(bp[1].x); bfr[2][1] = __float_as_uint(bp[1].y);
            bfr[3][0] = __float_as_uint(bp[1].z); bfr[3][1] = __float_as_uint(bp[1].w);
            #pragma unroll
            for (int mi = 0; mi < 4; mi++) {
                const uint32_t a0 = __float_as_uint(af[mi].x);
                const uint32_t a1 = __float_as_uint(af[mi].y);
                const uint32_t a2 = __float_as_uint(af[mi].z);
                const uint32_t a3 = __float_as_uint(af[mi].w);
                #pragma unroll
                for (int ni = 0; ni < 4; ni++)
                    mma16n8k8(acc[mi][ni], a0, a1, a2, a3, bfr[ni][0], bfr[ni][1]);
            }
        }
        cur++; if (cur == STAGES) cur = 0;
    }

    #pragma unroll
    for (int mi = 0; mi < 4; mi++) {
        const int row = o0 + wm * 64 + mi * 16 + gid;
        const float bias0 = g_bias[row];
        const float bias1 = g_bias[row + 8];
        float* y0 = y + ((size_t)b * COUT + row) * HW;
        #pragma unroll
        for (int ni = 0; ni < 4; ni++) {
            const int col = hw0 + (wn * 4 + ni) * 8 + tg * 2;
            if (col < HW) {
                float2 v0 = make_float2(acc[mi][ni][0] + bias0, acc[mi][ni][1] + bias0);
                float2 v1 = make_float2(acc[mi][ni][2] + bias1, acc[mi][ni][3] + bias1);
                *reinterpret_cast<float2*>(y0 + col) = v0;
                *reinterpret_cast<float2*>(y0 + (size_t)8 * HW + col) = v1;
            }
        }
    }
}

// ---------------- launch (serial) ----------------
extern "C" void kernel_launch(void* const* d_in, const int* in_sizes, int n_in,
                              void* d_out, int out_size) {
    const float* x    = (const float*)d_in[0];
    const float* fc_w = (const float*)d_in[1];
    const float* abn_g = (const float*)d_in[2];
    const float* abn_b = (const float*)d_in[3];
    const float* abn_m = (const float*)d_in[4];
    const float* abn_v = (const float*)d_in[5];
    const float* ch_w = (const float*)d_in[6];
    const float* ch_b = (const float*)d_in[7];
    const float* fl_w = (const float*)d_in[8];
    const float* fl_b = (const float*)d_in[9];
    const float* kn_w = (const float*)d_in[10];
    const float* kn_b = (const float*)d_in[11];
    const float* weight = (const float*)d_in[12];
    const float* bn_g = (const float*)d_in[13];
    const float* bn_b = (const float*)d_in[14];
    const float* bn_m = (const float*)d_in[15];
    const float* bn_v = (const float*)d_in[16];
    float* y = (float*)d_out;

    static bool attr_set = false;
    if (!attr_set) {
        cudaFuncSetAttribute(gemm_mma_kernel,
                             cudaFuncAttributeMaxDynamicSharedMemorySize, GEMM_SMEM_BYTES);
        attr_set = true;
    }

    prepack_kernel<<<BATCH * NKT8, 256>>>(x);   // 2048 blocks, pool fused

    attn_kernel<<<BATCH, 256>>>(fc_w, abn_g, abn_b, abn_m, abn_v,
                                ch_w, ch_b, fl_w, fl_b, kn_w, kn_b,
                                bn_g, bn_b, bn_m, bn_v);

    weff_kernel<<<NMT * NKT8 * 32 * 4 / 256, 256>>>(weight);   // 1024 blocks

    dim3 grid(COUT / BM, (HW + BN - 1) / BN, BATCH);  // (4, 25, 32)
    gemm_mma_kernel<<<grid, 256, GEMM_SMEM_BYTES>>>(y);
}

// round 11
// speedup vs baseline: 1.1826x; 1.0708x over previous
#include <cuda_runtime.h>
#include <math.h>
#include <cstdint>

#define EPSF 1e-5f

// Problem constants
#define BATCH 32
#define CIN   512
#define COUT  512
#define HW    3136   // 56*56
#define KNUM  4
#define ADIM  32

#define NMT  (COUT / 16)   // 32 m-tiles
#define NKT8 (CIN / 8)     // 64 k8-tiles
#define NTP  (HW / 16)     // 196 n-tile-pairs

// GEMM tiling
#define BM 128
#define BN 128
#define BKK 32
#define NIT (CIN / BKK)          // 16 mainloop iterations
#define STAGES 3
#define A_STAGE_FLOATS (8 * 4 * 32 * 4)    // 4096
#define B_STAGE_FLOATS (4 * 8 * 32 * 4)    // 4096
#define STAGE_FLOATS (A_STAGE_FLOATS + B_STAGE_FLOATS)
#define GEMM_SMEM_BYTES (STAGES * STAGE_FLOATS * 4)   // 98304 B

// prepack smem: 8 rows x (3136 + 8 pad) floats
#define PRE_SROW 3144
#define PREPACK_SMEM_BYTES (8 * PRE_SROW * 4)   // 100608 B

// ---------------- device scratch ----------------
__device__ float g_pooled[BATCH * CIN];
__device__ float g_ch[BATCH * CIN];
__device__ float g_rowscale[BATCH * COUT];
__device__ float g_kn[BATCH * KNUM];
__device__ float g_bias[COUT];
__device__ float g_weff[BATCH * NMT * NKT8 * 32 * 4];
__device__ float g_xpack[(size_t)BATCH * NKT8 * NTP * 32 * 4];

// ================= helpers =================
__device__ __forceinline__ float cvt_tf32(float v) {
    uint32_t u;
    asm("cvt.rna.tf32.f32 %0, %1;" : "=r"(u) : "f"(v));
    return __uint_as_float(u);
}

__device__ __forceinline__ void cp16(float* smem_dst, const float* gsrc, bool pred) {
    uint32_t s;
    asm("{ .reg .u64 t; cvta.to.shared.u64 t, %1; cvt.u32.u64 %0, t; }"
        : "=r"(s) : "l"(smem_dst));
    int sz = pred ? 16 : 0;
    asm volatile("cp.async.cg.shared.global [%0], [%1], 16, %2;"
                 :: "r"(s), "l"(gsrc), "r"(sz) : "memory");
}
#define CP_COMMIT() asm volatile("cp.async.commit_group;" ::: "memory")
#define CP_WAIT(n)  asm volatile("cp.async.wait_group %0;" :: "n"(n) : "memory")

__device__ __forceinline__ void mma16n8k8(float (&d)[4], const uint32_t a0, const uint32_t a1,
                                          const uint32_t a2, const uint32_t a3,
                                          const uint32_t b0, const uint32_t b1) {
    asm volatile(
        "mma.sync.aligned.m16n8k8.row.col.f32.tf32.tf32.f32 "
        "{%0,%1,%2,%3}, {%4,%5,%6,%7}, {%8,%9}, {%0,%1,%2,%3};"
        : "+f"(d[0]), "+f"(d[1]), "+f"(d[2]), "+f"(d[3])
        : "r"(a0), "r"(a1), "r"(a2), "r"(a3), "r"(b0), "r"(b1));
}

__device__ __forceinline__ float warp_sum(float v) {
    #pragma unroll
    for (int off = 16; off > 0; off >>= 1)
        v += __shfl_xor_sync(0xffffffffu, v, off);
    return v;
}

// ---------------- Kernel A: prepack x -> tf32 B-fragments, single sync -----
// block = (b, kt8); warp w owns full x row (kt8*8 + w). Pool fused (warp-local).
__global__ __launch_bounds__(256)
void prepack_kernel(const float* __restrict__ x) {
    extern __shared__ float sx[];   // [8][PRE_SROW]

    const int bx  = blockIdx.x;
    const int b   = bx >> 6;
    const int kt8 = bx & 63;
    const int tid = threadIdx.x;
    const int lane = tid & 31;
    const int w    = tid >> 5;

    const float4* Xr = reinterpret_cast<const float4*>(
        x + ((size_t)b * CIN + kt8 * 8 + w) * HW);
    float4* Op = reinterpret_cast<float4*>(g_xpack) +
                 ((size_t)(b * NKT8 + kt8) * NTP) * 32;

    // load full row (784 float4) + warp-local pool sum
    float psum = 0.f;
    float* srow = sx + w * PRE_SROW;
    for (int i = lane; i < HW / 4; i += 32) {
        float4 v = Xr[i];
        psum += v.x + v.y + v.z + v.w;
        *reinterpret_cast<float4*>(&srow[i * 4]) = v;
    }
    psum = warp_sum(psum);
    if (lane == 0) g_pooled[b * CIN + kt8 * 8 + w] = psum * (1.0f / HW);

    __syncthreads();

    // gather into B-fragment layout: all lanes of a warp share one ntp per round
    const int tg  = lane & 3;
    const int gid = lane >> 2;
    const float* r0 = sx + tg * PRE_SROW;
    const float* r1 = sx + (tg + 4) * PRE_SROW;
    #pragma unroll 5
    for (int r = 0; r < (NTP * 32 + 255) / 256; r++) {
        const int f = tid + 256 * r;
        const int ntpl = f >> 5;
        if (ntpl < NTP) {
            const int col0 = ntpl * 16 + gid;
            float4 o;
            o.x = cvt_tf32(r0[col0]);
            o.y = cvt_tf32(r1[col0]);
            o.z = cvt_tf32(r0[col0 + 8]);
            o.w = cvt_tf32(r1[col0 + 8]);
            Op[(size_t)ntpl * 32 + lane] = o;
        }
    }
}

// ---------------- Kernel B: attention heads (grid 32x2) ----------
__global__ __launch_bounds__(256)
void attn_kernel(const float* __restrict__ fc_w,
                 const float* __restrict__ abn_g, const float* __restrict__ abn_b,
                 const float* __restrict__ abn_m, const float* __restrict__ abn_v,
                 const float* __restrict__ ch_w, const float* __restrict__ ch_b,
                 const float* __restrict__ fl_w, const float* __restrict__ fl_b,
                 const float* __restrict__ kn_w, const float* __restrict__ kn_b,
                 const float* __restrict__ bn_g, const float* __restrict__ bn_b,
                 const float* __restrict__ bn_m, const float* __restrict__ bn_v) {
    __shared__ float sp[CIN];
    __shared__ float sh[ADIM];
    __shared__ float slog[KNUM];

    const int b = blockIdx.x;
    const int half = blockIdx.y;
    const int tid = threadIdx.x;
    const int wid = tid >> 5;
    const int lane = tid & 31;

    #pragma unroll
    for (int i = 0; i < CIN / 256; i++)
        sp[tid + 256 * i] = g_pooled[b * CIN + tid + 256 * i];
    __syncthreads();

    // h[a] (computed by both halves; tiny)
    #pragma unroll
    for (int i = 0; i < 4; i++) {
        const int a = wid + 8 * i;
        const float* fr = &fc_w[a * CIN];
        float s = 0.f;
        #pragma unroll
        for (int c = 0; c < CIN / 32; c++)
            s += sp[lane + 32 * c] * fr[lane + 32 * c];
        s = warp_sum(s);
        if (lane == 0) {
            float inv_a = abn_g[a] * rsqrtf(abn_v[a] + EPSF);
            s = (s - abn_m[a]) * inv_a + abn_b[a];
            sh[a] = fmaxf(s, 0.f);
        }
    }
    __syncthreads();

    const float hv = sh[lane];

    if (half == 0) {
        // channel attention
        for (int i = 0; i < 64; i++) {
            const int c = wid * 64 + i;
            float s = warp_sum(hv * ch_w[c * ADIM + lane]);
            if (lane == 0)
                g_ch[b * CIN + c] = 1.0f / (1.0f + __expf(-(s + ch_b[c])));
        }
    } else {
        // filter attention fused with BN scale
        for (int i = 0; i < 64; i++) {
            const int o = wid * 64 + i;
            float s = warp_sum(hv * fl_w[o * ADIM + lane]);
            if (lane == 0) {
                float fl = 1.0f / (1.0f + __expf(-(s + fl_b[o])));
                g_rowscale[b * COUT + o] = fl * bn_g[o] * rsqrtf(bn_v[o] + EPSF);
            }
        }
        if (wid == 0) {
            #pragma unroll
            for (int kk = 0; kk < KNUM; kk++) {
                float s = warp_sum(hv * kn_w[kk * ADIM + lane]);
                if (lane == 0) slog[kk] = s + kn_b[kk];
            }
            __syncwarp();
            if (lane == 0) {
                float m = fmaxf(fmaxf(slog[0], slog[1]), fmaxf(slog[2], slog[3]));
                float e0 = __expf(slog[0] - m), e1 = __expf(slog[1] - m);
                float e2 = __expf(slog[2] - m), e3 = __expf(slog[3] - m);
                float d = 1.0f / (e0 + e1 + e2 + e3);
                g_kn[b * KNUM + 0] = e0 * d;
                g_kn[b * KNUM + 1] = e1 * d;
                g_kn[b * KNUM + 2] = e2 * d;
                g_kn[b * KNUM + 3] = e3 * d;
            }
        }
        if (b == 0) {
            #pragma unroll
            for (int i = 0; i < COUT / 256; i++) {
                int o = tid + 256 * i;
                float inv = bn_g[o] * rsqrtf(bn_v[o] + EPSF);
                g_bias[o] = bn_b[o] - bn_m[o] * inv;
            }
        }
    }
}

// ---------------- Kernel C: effective weight, 4-way batch-split ----------------
__global__ __launch_bounds__(256)
void weff_kernel(const float* __restrict__ weight) {
    const int gidx = blockIdx.x * 256 + threadIdx.x;
    const int lane = gidx & 31;
    const int kt8 = (gidx >> 5) & (NKT8 - 1);
    const int mt  = (gidx >> 11) & (NMT - 1);
    const int bq  = gidx >> 16;            // 0..3

    const int gid = lane >> 2;
    const int tg  = lane & 3;
    const int o  = mt * 16 + gid;
    const int k  = kt8 * 8 + tg;

    float w[4][4];
    #pragma unroll
    for (int j = 0; j < KNUM; j++) {
        const float* wj = weight + ((size_t)j * COUT) * CIN;
        w[j][0] = wj[(size_t)o * CIN + k];
        w[j][1] = wj[(size_t)(o + 8) * CIN + k];
        w[j][2] = wj[(size_t)o * CIN + k + 4];
        w[j][3] = wj[(size_t)(o + 8) * CIN + k + 4];
    }

    float4* out = reinterpret_cast<float4*>(g_weff);
    const int b0 = bq * 8;
    #pragma unroll
    for (int bb = 0; bb < 8; bb++) {
        const int b = b0 + bb;
        const float kn0 = g_kn[b * KNUM + 0], kn1 = g_kn[b * KNUM + 1];
        const float kn2 = g_kn[b * KNUM + 2], kn3 = g_kn[b * KNUM + 3];
        const float rs0 = g_rowscale[b * COUT + o];
        const float rs1 = g_rowscale[b * COUT + o + 8];
        const float ch0 = g_ch[b * CIN + k];
        const float ch1 = g_ch[b * CIN + k + 4];

        float4 v;
        v.x = cvt_tf32(rs0 * ch0 * (kn0 * w[0][0] + kn1 * w[1][0] + kn2 * w[2][0] + kn3 * w[3][0]));
        v.y = cvt_tf32(rs1 * ch0 * (kn0 * w[0][1] + kn1 * w[1][1] + kn2 * w[2][1] + kn3 * w[3][1]));
        v.z = cvt_tf32(rs0 * ch1 * (kn0 * w[0][2] + kn1 * w[1][2] + kn2 * w[2][2] + kn3 * w[3][2]));
        v.w = cvt_tf32(rs1 * ch1 * (kn0 * w[0][3] + kn1 * w[1][3] + kn2 * w[2][3] + kn3 * w[3][3]));
        out[((size_t)(b * NMT + mt) * NKT8 + kt8) * 32 + lane] = v;
    }
}

// ---------------- Kernel D: mma.sync tf32 GEMM, both operands frag-packed ----
__global__ __launch_bounds__(256, 2)
void gemm_mma_kernel(float* __restrict__ y) {
    extern __shared__ float smem[];

    const int tid  = threadIdx.x;
    const int lane = tid & 31;
    const int wid  = tid >> 5;
    const int wm   = wid >> 2;
    const int wn   = wid & 3;
    const int gid  = lane >> 2;
    const int tg   = lane & 3;

    const int mt0 = blockIdx.x * (BM / 16);
    const int o0  = blockIdx.x * BM;
    const int hw0 = blockIdx.y * BN;
    const int ntp0 = blockIdx.y * (BN / 16);
    const int b   = blockIdx.z;

    const float4* Wg4 = reinterpret_cast<const float4*>(g_weff);
    size_t a_g[4];
    #pragma unroll
    for (int r = 0; r < 4; r++) {
        const int f = tid + 256 * r;
        const int mt = f >> 7, kt8l = (f >> 5) & 3, ln = f & 31;
        a_g[r] = ((size_t)(b * NMT + mt0 + mt) * NKT8 + kt8l) * 32 + ln;
    }
    const float4* Xp4 = reinterpret_cast<const float4*>(g_xpack);
    size_t b_g[4];
    bool b_pred[4];
    #pragma unroll
    for (int r = 0; r < 4; r++) {
        const int f = tid + 256 * r;
        const int kt8l = f >> 8, ntp = (f >> 5) & 7, ln = f & 31;
        b_g[r] = ((size_t)(b * NKT8 + kt8l) * NTP + ntp0 + ntp) * 32 + ln;
        b_pred[r] = (ntp0 + ntp) < NTP;
    }

    float acc[4][4][4];
    #pragma unroll
    for (int mi = 0; mi < 4; mi++)
        #pragma unroll
        for (int ni = 0; ni < 4; ni++)
            #pragma unroll
            for (int r = 0; r < 4; r++) acc[mi][ni][r] = 0.f;

    #pragma unroll
    for (int s = 0; s < STAGES - 1; s++) {
        float* As = smem + s * STAGE_FLOATS;
        float* Bs = As + A_STAGE_FLOATS;
        #pragma unroll
        for (int r = 0; r < 4; r++) {
            const int f = tid + 256 * r;
            cp16(&As[f * 4], (const float*)(Wg4 + a_g[r] + (size_t)s * 128), true);
            cp16(&Bs[f * 4], (const float*)(Xp4 + b_g[r] + (size_t)s * 4 * NTP * 32), b_pred[r]);
        }
        CP_COMMIT();
    }

    int cur = 0;
    for (int kc = 0; kc < NIT; kc++) {
        if (kc + 2 < NIT) { CP_WAIT(1); } else { CP_WAIT(0); }
        __syncthreads();

        if (kc + 2 < NIT) {
            int s = cur + 2; if (s >= STAGES) s -= STAGES;
            float* As = smem + s * STAGE_FLOATS;
            float* Bs = As + A_STAGE_FLOATS;
            #pragma unroll
            for (int r = 0; r < 4; r++) {
                const int f = tid + 256 * r;
                cp16(&As[f * 4], (const float*)(Wg4 + a_g[r] + (size_t)(kc + 2) * 128), true);
                cp16(&Bs[f * 4], (const float*)(Xp4 + b_g[r] + (size_t)(kc + 2) * 4 * NTP * 32), b_pred[r]);
            }
            CP_COMMIT();
        }

        const float* As = smem + cur * STAGE_FLOATS;
        const float4* Af = reinterpret_cast<const float4*>(As);
        const float4* Bf4 = reinterpret_cast<const float4*>(As + A_STAGE_FLOATS);

        #pragma unroll
        for (int kt = 0; kt < 4; kt++) {
            float4 af[4];
            #pragma unroll
            for (int mi = 0; mi < 4; mi++)
                af[mi] = Af[((wm * 4 + mi) * 4 + kt) * 32 + lane];
            float4 bp[2];
            #pragma unroll
            for (int p = 0; p < 2; p++)
                bp[p] = Bf4[((kt * 8) + wn * 2 + p) * 32 + lane];
            uint32_t bfr[4][2];
            bfr[0][0] = __float_as_uint(bp[0].x); bfr[0][1] = __float_as_uint(bp[0].y);
            bfr[1][0] = __float_as_uint(bp[0].z); bfr[1][1] = __float_as_uint(bp[0].w);
            bfr[2][0] = __float_as_uint(bp[1].x); bfr[2][1] = __float_as_uint(bp[1].y);
            bfr[3][0] = __float_as_uint(bp[1].z); bfr[3][1] = __float_as_uint(bp[1].w);
            #pragma unroll
            for (int mi = 0; mi < 4; mi++) {
                const uint32_t a0 = __float_as_uint(af[mi].x);
                const uint32_t a1 = __float_as_uint(af[mi].y);
                const uint32_t a2 = __float_as_uint(af[mi].z);
                const uint32_t a3 = __float_as_uint(af[mi].w);
                #pragma unroll
                for (int ni = 0; ni < 4; ni++)
                    mma16n8k8(acc[mi][ni], a0, a1, a2, a3, bfr[ni][0], bfr[ni][1]);
            }
        }
        cur++; if (cur == STAGES) cur = 0;
    }

    #pragma unroll
    for (int mi = 0; mi < 4; mi++) {
        const int row = o0 + wm * 64 + mi * 16 + gid;
        const float bias0 = g_bias[row];
        const float bias1 = g_bias[row + 8];
        float* y0 = y + ((size_t)b * COUT + row) * HW;
        #pragma unroll
        for (int ni = 0; ni < 4; ni++) {
            const int col = hw0 + (wn * 4 + ni) * 8 + tg * 2;
            if (col < HW) {
                float2 v0 = make_float2(acc[mi][ni][0] + bias0, acc[mi][ni][1] + bias0);
                float2 v1 = make_float2(acc[mi][ni][2] + bias1, acc[mi][ni][3] + bias1);
                *reinterpret_cast<float2*>(y0 + col) = v0;
                *reinterpret_cast<float2*>(y0 + (size_t)8 * HW + col) = v1;
            }
        }
    }
}

// ---------------- launch (serial) ----------------
extern "C" void kernel_launch(void* const* d_in, const int* in_sizes, int n_in,
                              void* d_out, int out_size) {
    const float* x    = (const float*)d_in[0];
    const float* fc_w = (const float*)d_in[1];
    const float* abn_g = (const float*)d_in[2];
    const float* abn_b = (const float*)d_in[3];
    const float* abn_m = (const float*)d_in[4];
    const float* abn_v = (const float*)d_in[5];
    const float* ch_w = (const float*)d_in[6];
    const float* ch_b = (const float*)d_in[7];
    const float* fl_w = (const float*)d_in[8];
    const float* fl_b = (const float*)d_in[9];
    const float* kn_w = (const float*)d_in[10];
    const float* kn_b = (const float*)d_in[11];
    const float* weight = (const float*)d_in[12];
    const float* bn_g = (const float*)d_in[13];
    const float* bn_b = (const float*)d_in[14];
    const float* bn_m = (const float*)d_in[15];
    const float* bn_v = (const float*)d_in[16];
    float* y = (float*)d_out;

    static bool attr_set = false;
    if (!attr_set) {
        cudaFuncSetAttribute(gemm_mma_kernel,
                             cudaFuncAttributeMaxDynamicSharedMemorySize, GEMM_SMEM_BYTES);
        cudaFuncSetAttribute(prepack_kernel,
                             cudaFuncAttributeMaxDynamicSharedMemorySize, PREPACK_SMEM_BYTES);
        attr_set = true;
    }

    prepack_kernel<<<BATCH * NKT8, 256, PREPACK_SMEM_BYTES>>>(x);   // 2048 blocks

    attn_kernel<<<dim3(BATCH, 2), 256>>>(fc_w, abn_g, abn_b, abn_m, abn_v,
                                         ch_w, ch_b, fl_w, fl_b, kn_w, kn_b,
                                         bn_g, bn_b, bn_m, bn_v);

    weff_kernel<<<NMT * NKT8 * 32 * 4 / 256, 256>>>(weight);   // 1024 blocks

    dim3 grid(COUT / BM, (HW + BN - 1) / BN, BATCH);  // (4, 25, 32)
    gemm_mma_kernel<<<grid, 256, GEMM_SMEM_BYTES>>>(y);
}